// round 7
// baseline (speedup 1.0000x reference)
#include <cuda_runtime.h>
#include <cstdint>

// Problem constants (fixed by reference setup_inputs)
#define B_SZ   16
#define T_IN   512
#define D_DIM  768
#define D4     (D_DIM / 4)       // 192 float4 per row = blockDim
#define PH     4                 // phonemes per block
#define NBLK   (T_IN / PH)       // 128 blocks per batch

// Single fused kernel. Prologue: thread j<128 loads durations[4j..4j+3] as
// int4; prefix-before-block = sum of thread-sums for j<blk (exact int4
// boundary), block's own 4 durations = thread j==blk's int4. Then scatter.
// durations are int32 on device (JAX default config downgrades int64).
__global__ void __launch_bounds__(D4) lr_fused2_kernel(
    const float4* __restrict__ hidden,
    const int*    __restrict__ durations,
    float4*       __restrict__ out,
    int t_out) {
    __shared__ int s_red_before[4], s_red_all[4];
    __shared__ int s_mydur[PH];

    const int blk  = blockIdx.x;            // 0..NBLK-1
    const int b    = blockIdx.y;
    const int i0   = blk * PH;
    const int tid  = threadIdx.x;           // 0..191
    const int lane = tid & 31;
    const int wid  = tid >> 5;              // 0..5

    // ---- Phase 0: row loads (depend only on blockIdx -> issue immediately) ----
    float4 v[PH];
    #pragma unroll
    for (int k = 0; k < PH; ++k)
        v[k] = __ldg(hidden + ((size_t)b * T_IN + i0 + k) * D4 + tid);

    // ---- Phase 1: duration prefix via one int4 per thread (threads 0..127) ----
    int s_all = 0, s_before = 0;
    if (tid < NBLK) {
        const int4 d = __ldg((const int4*)(durations + b * T_IN) + tid);
        const int s = d.x + d.y + d.z + d.w;
        s_all = s;
        s_before = (tid < blk) ? s : 0;
        if (tid == blk) {
            s_mydur[0] = d.x; s_mydur[1] = d.y;
            s_mydur[2] = d.z; s_mydur[3] = d.w;
        }
    }
    // warp reduce (warps 0..3 hold data; 4,5 contribute zeros)
    #pragma unroll
    for (int off = 16; off > 0; off >>= 1) {
        s_before += __shfl_down_sync(0xFFFFFFFFu, s_before, off);
        s_all    += __shfl_down_sync(0xFFFFFFFFu, s_all, off);
    }
    if (lane == 0 && wid < 4) { s_red_before[wid] = s_before; s_red_all[wid] = s_all; }
    __syncthreads();

    const int base  = s_red_before[0] + s_red_before[1] + s_red_before[2] + s_red_before[3];
    const int total = s_red_all[0] + s_red_all[1] + s_red_all[2] + s_red_all[3];

    // ---- Phase 2: scatter PH rows to their output frame ranges ----
    float4* const out_b = out + (size_t)b * t_out * D4;
    int run = base;
    #pragma unroll
    for (int k = 0; k < PH; ++k) {
        const int dur = s_mydur[k];
        float4* o = out_b + (size_t)run * D4 + tid;
        #pragma unroll 4
        for (int j = 0; j < dur; ++j)
            o[(size_t)j * D4] = v[k];
        run += dur;
    }

    // ---- Phase 3: padding frames [total, t_out), strided across blocks ----
    const float4 z = make_float4(0.f, 0.f, 0.f, 0.f);
    for (int t = total + blk; t < t_out; t += NBLK)
        out_b[(size_t)t * D4 + tid] = z;
}

extern "C" void kernel_launch(void* const* d_in, const int* in_sizes, int n_in,
                              void* d_out, int out_size) {
    const float* hidden    = (const float*)d_in[0];  // (B, T_IN, D) f32
    const int*   durations = (const int*)d_in[1];    // (B, T_IN) int32

    const int t_out = out_size / (B_SZ * D_DIM);

    dim3 grid(NBLK, B_SZ);
    lr_fused2_kernel<<<grid, D4>>>((const float4*)hidden, durations,
                                   (float4*)d_out, t_out);
}

// round 8
// speedup vs baseline: 1.0085x; 1.0085x over previous
#include <cuda_runtime.h>
#include <cstdint>

// Problem constants (fixed by reference setup_inputs)
#define B_SZ   16
#define T_IN   512
#define D_DIM  768
#define PH     4                 // phonemes per block
#define NBLK   (T_IN / PH)       // 128 blocks per batch
#define ROW_BYTES 3072           // 768 * 4
#define CHUNKS 96                // 32B chunks per row
#define NTHREADS 192             // 2 half-blocks of 96

// 256-bit vector helpers (sm_100a+: ld/st.global.v8.f32)
struct __align__(32) f8 { float x0,x1,x2,x3,x4,x5,x6,x7; };

__device__ __forceinline__ f8 ldg_v8(const void* p) {
    f8 r;
    asm volatile("ld.global.v8.f32 {%0,%1,%2,%3,%4,%5,%6,%7}, [%8];"
        : "=f"(r.x0), "=f"(r.x1), "=f"(r.x2), "=f"(r.x3),
          "=f"(r.x4), "=f"(r.x5), "=f"(r.x6), "=f"(r.x7)
        : "l"(p));
    return r;
}
__device__ __forceinline__ void stg_v8(void* p, const f8& r) {
    asm volatile("st.global.v8.f32 [%0], {%1,%2,%3,%4,%5,%6,%7,%8};"
        :: "l"(p),
           "f"(r.x0), "f"(r.x1), "f"(r.x2), "f"(r.x3),
           "f"(r.x4), "f"(r.x5), "f"(r.x6), "f"(r.x7)
        : "memory");
}

// Single fused kernel, 256-bit memory ops.
// Half-block h (warps 0-2 / 3-5) owns phonemes i0+2h, i0+2h+1; thread covers
// one 32B chunk of the 3072B row. durations are int32 on device.
__global__ void __launch_bounds__(NTHREADS) lr_v8_kernel(
    const char* __restrict__ hidden,
    const int*  __restrict__ durations,
    char*       __restrict__ out,
    int t_out) {
    __shared__ int s_red_before[4], s_red_all[4];
    __shared__ int s_mydur[PH];

    const int blk  = blockIdx.x;            // 0..NBLK-1
    const int b    = blockIdx.y;
    const int i0   = blk * PH;
    const int tid  = threadIdx.x;           // 0..191
    const int lane = tid & 31;
    const int wid  = tid >> 5;              // 0..5
    const int h    = tid / CHUNKS;          // half-block 0/1 (warp-aligned)
    const int c    = tid % CHUNKS;          // 32B chunk index

    // ---- Phase 0: this half's two row-chunks (issue immediately) ----
    const char* hid_b = hidden + ((size_t)b * T_IN + i0 + 2 * h) * ROW_BYTES + c * 32;
    f8 vA = ldg_v8(hid_b);
    f8 vB = ldg_v8(hid_b + ROW_BYTES);

    // ---- Phase 1: duration prefix via one int4 per thread (threads 0..127) ----
    int s_all = 0, s_before = 0;
    if (tid < NBLK) {
        const int4 d = __ldg((const int4*)(durations + b * T_IN) + tid);
        const int s = d.x + d.y + d.z + d.w;
        s_all = s;
        s_before = (tid < blk) ? s : 0;
        if (tid == blk) {
            s_mydur[0] = d.x; s_mydur[1] = d.y;
            s_mydur[2] = d.z; s_mydur[3] = d.w;
        }
    }
    #pragma unroll
    for (int off = 16; off > 0; off >>= 1) {
        s_before += __shfl_down_sync(0xFFFFFFFFu, s_before, off);
        s_all    += __shfl_down_sync(0xFFFFFFFFu, s_all, off);
    }
    if (lane == 0 && wid < 4) { s_red_before[wid] = s_before; s_red_all[wid] = s_all; }
    __syncthreads();

    const int base  = s_red_before[0] + s_red_before[1] + s_red_before[2] + s_red_before[3];
    const int total = s_red_all[0] + s_red_all[1] + s_red_all[2] + s_red_all[3];

    const int dA = s_mydur[2 * h];
    const int dB = s_mydur[2 * h + 1];
    const int start_h = base + (h ? (s_mydur[0] + s_mydur[1]) : 0);

    // ---- Phase 2: scatter this half's 2 rows ----
    char* const out_b = out + (size_t)b * t_out * ROW_BYTES;
    char* o = out_b + (size_t)start_h * ROW_BYTES + c * 32;
    #pragma unroll 4
    for (int j = 0; j < dA; ++j)
        stg_v8(o + (size_t)j * ROW_BYTES, vA);
    o += (size_t)dA * ROW_BYTES;
    #pragma unroll 4
    for (int j = 0; j < dB; ++j)
        stg_v8(o + (size_t)j * ROW_BYTES, vB);

    // ---- Phase 3: padding frames [total, t_out), one frame per half-block ----
    f8 z; z.x0=z.x1=z.x2=z.x3=z.x4=z.x5=z.x6=z.x7=0.f;
    for (int t = total + 2 * blk + h; t < t_out; t += 2 * NBLK)
        stg_v8(out_b + (size_t)t * ROW_BYTES + c * 32, z);
}

extern "C" void kernel_launch(void* const* d_in, const int* in_sizes, int n_in,
                              void* d_out, int out_size) {
    const char* hidden    = (const char*)d_in[0];  // (B, T_IN, D) f32
    const int*  durations = (const int*)d_in[1];   // (B, T_IN) int32

    const int t_out = out_size / (B_SZ * D_DIM);

    dim3 grid(NBLK, B_SZ);
    lr_v8_kernel<<<grid, NTHREADS>>>(hidden, durations, (char*)d_out, t_out);
}